// round 6
// baseline (speedup 1.0000x reference)
#include <cuda_runtime.h>
#include <cstdint>

#define BATCH        32768
#define FEAT_DIM     512
#define NUM_CLASSES  1000
#define KC           2
#define WARPS_PER_BLOCK 8
#define THREADS   (WARPS_PER_BLOCK * 32)
#define CAP          128                      // max bin size (mean 33, ~5sigma=60)
#define SAMPLES_PER_BLOCK 32                  // 8 warps * 4 samples
#define CHUNKS_PER_CLASS (CAP / SAMPLES_PER_BLOCK)   // 4
#define MAIN_BLOCKS  (NUM_CLASSES * CHUNKS_PER_CLASS)  // 4000

// Scratch via __device__ globals (allocation-free).
__device__ double        g_acc;
__device__ int           g_is64;
__device__ unsigned int  g_count;
__device__ int           g_cursor[NUM_CLASSES];
__device__ int           g_slot[NUM_CLASSES * CAP];

// K0: detect label dtype (int32 vs int64) + zero cursors & accumulators.
// 512 threads read the 512 odd 32-bit words of the first 4 KB (in-bounds for
// either dtype). int64 little-endian small labels => all-zero high words.
__global__ __launch_bounds__(512) void mcl_prep(const int* __restrict__ labels_words) {
    const int v = labels_words[2 * threadIdx.x + 1];
    const int any_nz = __syncthreads_or(v != 0);
    for (int i = threadIdx.x; i < NUM_CLASSES; i += 512) g_cursor[i] = 0;
    if (threadIdx.x == 0) {
        g_is64 = any_nz ? 0 : 1;
        g_acc = 0.0;
        g_count = 0u;
    }
}

// K1: scatter sample indices into per-class bins.
__global__ __launch_bounds__(1024) void mcl_scatter(const void* __restrict__ labels) {
    const int i = blockIdx.x * 1024 + threadIdx.x;
    if (i >= BATCH) return;
    long long lbl;
    if (g_is64) lbl = ((const long long*)labels)[i];
    else        lbl = (long long)((const int*)labels)[i];
    if (lbl < 0 || lbl >= NUM_CLASSES) lbl = 0;     // defensive clamp
    int pos = atomicAdd(&g_cursor[(int)lbl], 1);
    if (pos < CAP) g_slot[(int)lbl * CAP + pos] = i;
}

// K2: one class per block; centers live in registers, only x streams.
__global__ __launch_bounds__(THREADS, 4) void mcl_main(
    const float* __restrict__ x,
    const float* __restrict__ centers,
    float*       __restrict__ out)
{
    const int cls   = blockIdx.x / CHUNKS_PER_CLASS;
    const int chunk = blockIdx.x % CHUNKS_PER_CLASS;
    const int lane = threadIdx.x & 31;
    const int warp_local = threadIdx.x >> 5;

    int count = g_cursor[cls];
    if (count > CAP) count = CAP;
    const int base = chunk * SAMPLES_PER_BLOCK + warp_local * 4;   // this warp's 4 slots

    float sum_min = 0.0f;

    if (base < count) {
        // Load this class's two centers ONCE into registers (lane-sliced).
        const float4* __restrict__ c0 = reinterpret_cast<const float4*>(
            centers + (size_t)cls * (KC * FEAT_DIM));
        const float4* __restrict__ c1 = c0 + (FEAT_DIM / 4);
        float4 a[4], b[4];
        #pragma unroll
        for (int i = 0; i < 4; i++) a[i] = c0[lane + 32 * i];
        #pragma unroll
        for (int i = 0; i < 4; i++) b[i] = c1[lane + 32 * i];

        // Prefetch up to 4 slot indices in one coalesced access.
        int my_idx = 0;
        if (lane < 4 && base + lane < count)
            my_idx = g_slot[cls * CAP + base + lane];

        const int n = min(4, count - base);
        #pragma unroll
        for (int s = 0; s < 4; s++) {
            if (s >= n) break;
            const int idx = __shfl_sync(0xffffffffu, my_idx, s);
            const float4* __restrict__ xr = reinterpret_cast<const float4*>(
                x + (size_t)idx * FEAT_DIM);

            float d0 = 0.0f, d1 = 0.0f;
            #pragma unroll
            for (int i = 0; i < 4; i++) {
                const float4 xv = xr[lane + 32 * i];
                float t;
                t = xv.x - a[i].x; d0 = fmaf(t, t, d0);
                t = xv.y - a[i].y; d0 = fmaf(t, t, d0);
                t = xv.z - a[i].z; d0 = fmaf(t, t, d0);
                t = xv.w - a[i].w; d0 = fmaf(t, t, d0);
                t = xv.x - b[i].x; d1 = fmaf(t, t, d1);
                t = xv.y - b[i].y; d1 = fmaf(t, t, d1);
                t = xv.z - b[i].z; d1 = fmaf(t, t, d1);
                t = xv.w - b[i].w; d1 = fmaf(t, t, d1);
            }
            #pragma unroll
            for (int off = 16; off > 0; off >>= 1) {
                d0 += __shfl_xor_sync(0xffffffffu, d0, off);
                d1 += __shfl_xor_sync(0xffffffffu, d1, off);
            }
            sum_min += fminf(d0, d1);
        }
    }

    __shared__ float s_part[WARPS_PER_BLOCK];
    if (lane == 0) s_part[warp_local] = sum_min;
    __syncthreads();

    if (threadIdx.x == 0) {
        float block_sum = 0.0f;
        #pragma unroll
        for (int i = 0; i < WARPS_PER_BLOCK; i++) block_sum += s_part[i];
        if (block_sum != 0.0f) atomicAdd(&g_acc, (double)block_sum);
        __threadfence();
        unsigned int done = atomicAdd(&g_count, 1u);
        if (done == gridDim.x - 1) {
            out[0] = (float)(g_acc / (double)BATCH);
        }
    }
}

extern "C" void kernel_launch(void* const* d_in, const int* in_sizes, int n_in,
                              void* d_out, int out_size)
{
    // Identify inputs by element count (robust to ordering):
    //   x: 32768*512 = 16777216, centers: 2000*512 = 1024000, labels: 32768.
    const float* x       = nullptr;
    const void*  labels  = nullptr;
    const float* centers = nullptr;
    for (int i = 0; i < n_in; i++) {
        if (in_sizes[i] == BATCH * FEAT_DIM)                 x = (const float*)d_in[i];
        else if (in_sizes[i] == NUM_CLASSES * KC * FEAT_DIM) centers = (const float*)d_in[i];
        else if (in_sizes[i] == BATCH)                       labels = d_in[i];
    }
    float* out = (float*)d_out;

    mcl_prep<<<1, 512>>>((const int*)labels);
    mcl_scatter<<<(BATCH + 1023) / 1024, 1024>>>(labels);
    mcl_main<<<MAIN_BLOCKS, THREADS>>>(x, centers, out);
}

// round 7
// speedup vs baseline: 1.1877x; 1.1877x over previous
#include <cuda_runtime.h>
#include <cstdint>

#define BATCH        32768
#define FEAT_DIM     512
#define NUM_CLASSES  1000
#define KC           2
#define WARPS_PER_BLOCK 8
#define THREADS   (WARPS_PER_BLOCK * 32)
#define CAP          128     // max bin size (mean 32.8, sigma 5.7; overflow -> dropped -> rel_err, never OOB)

// Scratch via __device__ globals (allocation-free, static zero-init).
__device__ double        g_acc;
__device__ unsigned int  g_count;
__device__ int           g_cursor[NUM_CLASSES];
__device__ int           g_slot[NUM_CLASSES * CAP];

// K1: scatter sample indices into per-class bins.
// Dtype detection (int32 vs int64 labels) is done per-block: every block reads
// the 512 odd 32-bit words of the first 4 KB (in-bounds either way; the lines
// are L2-resident after block 0). int64 little-endian labels in [0,1000) have
// all-zero high words; int32 random labels cannot.
// g_cursor is zero on entry: statically on call 1, reset by K2's last block after.
__global__ __launch_bounds__(1024) void mcl_scatter(const void* __restrict__ labels) {
    const int tid = threadIdx.x;
    int v = 0;
    if (tid < 512) v = ((const int*)labels)[2 * tid + 1];
    const int is64 = __syncthreads_or(v != 0) ? 0 : 1;

    const int i = blockIdx.x * 1024 + tid;
    if (i >= BATCH) return;
    long long lbl;
    if (is64) lbl = ((const long long*)labels)[i];
    else      lbl = (long long)((const int*)labels)[i];
    if (lbl < 0 || lbl >= NUM_CLASSES) lbl = 0;     // defensive clamp
    int pos = atomicAdd(&g_cursor[(int)lbl], 1);
    if (pos < CAP) g_slot[(int)lbl * CAP + pos] = i;
}

// K2: one class per block. Each warp loads the class's 2 centers ONCE into
// registers, then strides over the bin 4 samples at a time. x loads are
// index-prefetched and independent -> deep MLP, no dependent gather chain.
// Last block finalizes the mean AND resets all state for the next replay.
__global__ __launch_bounds__(THREADS, 4) void mcl_main(
    const float* __restrict__ x,
    const float* __restrict__ centers,
    float*       __restrict__ out)
{
    const int cls  = blockIdx.x;
    const int lane = threadIdx.x & 31;
    const int warp_local = threadIdx.x >> 5;

    int count = g_cursor[cls];
    if (count > CAP) count = CAP;

    float sum_min = 0.0f;

    if (warp_local * 4 < count) {
        // Class centers -> registers (lane-sliced), loaded once per warp.
        const float4* __restrict__ c0 = reinterpret_cast<const float4*>(
            centers + (size_t)cls * (KC * FEAT_DIM));
        const float4* __restrict__ c1 = c0 + (FEAT_DIM / 4);
        float4 a[4], b[4];
        #pragma unroll
        for (int i = 0; i < 4; i++) a[i] = c0[lane + 32 * i];
        #pragma unroll
        for (int i = 0; i < 4; i++) b[i] = c1[lane + 32 * i];

        for (int sbase = warp_local * 4; sbase < count; sbase += WARPS_PER_BLOCK * 4) {
            // Prefetch up to 4 slot indices in one coalesced access.
            int my_idx = 0;
            if (lane < 4 && sbase + lane < count)
                my_idx = g_slot[cls * CAP + sbase + lane];
            const int n = min(4, count - sbase);

            #pragma unroll
            for (int s = 0; s < 4; s++) {
                if (s >= n) break;
                const int idx = __shfl_sync(0xffffffffu, my_idx, s);
                const float4* __restrict__ xr = reinterpret_cast<const float4*>(
                    x + (size_t)idx * FEAT_DIM);

                float d0 = 0.0f, d1 = 0.0f;
                #pragma unroll
                for (int i = 0; i < 4; i++) {
                    const float4 xv = xr[lane + 32 * i];
                    float t;
                    t = xv.x - a[i].x; d0 = fmaf(t, t, d0);
                    t = xv.y - a[i].y; d0 = fmaf(t, t, d0);
                    t = xv.z - a[i].z; d0 = fmaf(t, t, d0);
                    t = xv.w - a[i].w; d0 = fmaf(t, t, d0);
                    t = xv.x - b[i].x; d1 = fmaf(t, t, d1);
                    t = xv.y - b[i].y; d1 = fmaf(t, t, d1);
                    t = xv.z - b[i].z; d1 = fmaf(t, t, d1);
                    t = xv.w - b[i].w; d1 = fmaf(t, t, d1);
                }
                #pragma unroll
                for (int off = 16; off > 0; off >>= 1) {
                    d0 += __shfl_xor_sync(0xffffffffu, d0, off);
                    d1 += __shfl_xor_sync(0xffffffffu, d1, off);
                }
                sum_min += fminf(d0, d1);
            }
        }
    }

    __shared__ float s_part[WARPS_PER_BLOCK];
    if (lane == 0) s_part[warp_local] = sum_min;
    __syncthreads();

    if (threadIdx.x == 0) {
        float block_sum = 0.0f;
        #pragma unroll
        for (int i = 0; i < WARPS_PER_BLOCK; i++) block_sum += s_part[i];
        if (block_sum != 0.0f) atomicAdd(&g_acc, (double)block_sum);
        __threadfence();
        unsigned int done = atomicAdd(&g_count, 1u);
        s_part[0] = (done == gridDim.x - 1) ? 1.0f : 0.0f;
    }
    __syncthreads();

    // Last block: finalize output, then reset ALL state for the next call.
    if (s_part[0] != 0.0f) {
        for (int i = threadIdx.x; i < NUM_CLASSES; i += THREADS) g_cursor[i] = 0;
        if (threadIdx.x == 0) {
            out[0] = (float)(g_acc / (double)BATCH);
            g_acc = 0.0;
            g_count = 0u;
        }
    }
}

extern "C" void kernel_launch(void* const* d_in, const int* in_sizes, int n_in,
                              void* d_out, int out_size)
{
    // Identify inputs by element count (robust to ordering):
    //   x: 32768*512 = 16777216, centers: 2000*512 = 1024000, labels: 32768.
    const float* x       = nullptr;
    const void*  labels  = nullptr;
    const float* centers = nullptr;
    for (int i = 0; i < n_in; i++) {
        if (in_sizes[i] == BATCH * FEAT_DIM)                 x = (const float*)d_in[i];
        else if (in_sizes[i] == NUM_CLASSES * KC * FEAT_DIM) centers = (const float*)d_in[i];
        else if (in_sizes[i] == BATCH)                       labels = d_in[i];
    }
    float* out = (float*)d_out;

    mcl_scatter<<<(BATCH + 1023) / 1024, 1024>>>(labels);
    mcl_main<<<NUM_CLASSES, THREADS>>>(x, centers, out);
}

// round 8
// speedup vs baseline: 1.3685x; 1.1522x over previous
#include <cuda_runtime.h>
#include <cstdint>

#define BATCH        32768
#define FEAT_DIM     512
#define NUM_CLASSES  1000
#define KC           2
#define THREADS      128
#define WARPS_PER_BLOCK (THREADS / 32)
#define SPW          16                          // samples per warp
#define BLOCKS       (BATCH / (WARPS_PER_BLOCK * SPW))   // 512

// Scratch via __device__ globals (allocation-free, static zero-init; the last
// block resets them after finalizing, so every replay starts clean).
__device__ double        g_acc;
__device__ unsigned int  g_count;

__global__ __launch_bounds__(THREADS, 4) void mcl_main(
    const float* __restrict__ x,
    const void*  __restrict__ labels,
    const float* __restrict__ centers,
    float*       __restrict__ out)
{
    const int tid  = threadIdx.x;
    const int lane = tid & 31;
    const int warp_local = tid >> 5;

    // ---- label dtype detection (int32 vs int64), per block, ~free ----
    // Read the 512 odd 32-bit words of the first 4 KB (in-bounds either way).
    // int64 little-endian labels in [0,1000) have all-zero high words.
    int v = 0;
    #pragma unroll
    for (int k = 0; k < 512 / THREADS; k++)
        v |= ((const int*)labels)[2 * (tid + k * THREADS) + 1];
    const int is64 = __syncthreads_or(v != 0) ? 0 : 1;

    const int warp_id = blockIdx.x * WARPS_PER_BLOCK + warp_local;
    const int base = warp_id * SPW;

    // ---- prefetch all 16 labels in one coalesced access ----
    int my_lbl = 0;
    if (lane < SPW) {
        long long l;
        if (is64) l = ((const long long*)labels)[base + lane];
        else      l = (long long)((const int*)labels)[base + lane];
        if (l < 0 || l >= NUM_CLASSES) l = 0;    // defensive clamp
        my_lbl = (int)l;
    }

    // ---- ping-pong register buffers: x row + both centers (96 regs) ----
    float4 xb[2][4], ab[2][4], bb[2][4];

    #define PREFETCH(s, buf)                                                   \
        do {                                                                   \
            const float4* __restrict__ xr_ = reinterpret_cast<const float4*>( \
                x + (size_t)(base + (s)) * FEAT_DIM);                          \
            const int lbl_ = __shfl_sync(0xffffffffu, my_lbl, (s));            \
            const float4* __restrict__ c0_ = reinterpret_cast<const float4*>( \
                centers + (size_t)lbl_ * (KC * FEAT_DIM));                     \
            const float4* __restrict__ c1_ = c0_ + (FEAT_DIM / 4);             \
            _Pragma("unroll")                                                  \
            for (int i_ = 0; i_ < 4; i_++) {                                   \
                xb[buf][i_] = xr_[lane + 32 * i_];                             \
                ab[buf][i_] = c0_[lane + 32 * i_];                             \
                bb[buf][i_] = c1_[lane + 32 * i_];                             \
            }                                                                  \
        } while (0)

    PREFETCH(0, 0);

    float total = 0.0f;
    #pragma unroll
    for (int s = 0; s < SPW; s++) {
        const int cur = s & 1;
        // Issue next sample's 12 loads BEFORE computing: they fly during the
        // FMA chain + shfl tree, keeping the memory queue non-empty.
        if (s + 1 < SPW) PREFETCH(s + 1, (s + 1) & 1);

        float d0 = 0.0f, d1 = 0.0f;
        #pragma unroll
        for (int i = 0; i < 4; i++) {
            const float4 xv = xb[cur][i];
            const float4 a  = ab[cur][i];
            const float4 b  = bb[cur][i];
            float t;
            t = xv.x - a.x; d0 = fmaf(t, t, d0);
            t = xv.y - a.y; d0 = fmaf(t, t, d0);
            t = xv.z - a.z; d0 = fmaf(t, t, d0);
            t = xv.w - a.w; d0 = fmaf(t, t, d0);
            t = xv.x - b.x; d1 = fmaf(t, t, d1);
            t = xv.y - b.y; d1 = fmaf(t, t, d1);
            t = xv.z - b.z; d1 = fmaf(t, t, d1);
            t = xv.w - b.w; d1 = fmaf(t, t, d1);
        }
        #pragma unroll
        for (int off = 16; off > 0; off >>= 1) {
            d0 += __shfl_xor_sync(0xffffffffu, d0, off);
            d1 += __shfl_xor_sync(0xffffffffu, d1, off);
        }
        total += fminf(d0, d1);
    }
    #undef PREFETCH

    // ---- block reduce + single device accumulate ----
    __shared__ float s_part[WARPS_PER_BLOCK];
    __shared__ float s_last;
    if (lane == 0) s_part[warp_local] = total;
    __syncthreads();

    if (tid == 0) {
        float block_sum = 0.0f;
        #pragma unroll
        for (int i = 0; i < WARPS_PER_BLOCK; i++) block_sum += s_part[i];
        atomicAdd(&g_acc, (double)block_sum);
        __threadfence();
        unsigned int done = atomicAdd(&g_count, 1u);
        s_last = (done == gridDim.x - 1) ? 1.0f : 0.0f;
    }
    __syncthreads();

    // Last block: finalize mean, then reset state for the next replay.
    if (s_last != 0.0f && tid == 0) {
        out[0] = (float)(g_acc / (double)BATCH);
        g_acc = 0.0;
        g_count = 0u;
    }
}

extern "C" void kernel_launch(void* const* d_in, const int* in_sizes, int n_in,
                              void* d_out, int out_size)
{
    // Identify inputs by element count (robust to ordering):
    //   x: 32768*512 = 16777216, centers: 2000*512 = 1024000, labels: 32768.
    const float* x       = nullptr;
    const void*  labels  = nullptr;
    const float* centers = nullptr;
    for (int i = 0; i < n_in; i++) {
        if (in_sizes[i] == BATCH * FEAT_DIM)                 x = (const float*)d_in[i];
        else if (in_sizes[i] == NUM_CLASSES * KC * FEAT_DIM) centers = (const float*)d_in[i];
        else if (in_sizes[i] == BATCH)                       labels = d_in[i];
    }
    float* out = (float*)d_out;

    mcl_main<<<BLOCKS, THREADS>>>(x, labels, centers, out);
}

// round 9
// speedup vs baseline: 1.3709x; 1.0017x over previous
#include <cuda_runtime.h>
#include <cstdint>

#define BATCH        32768
#define FEAT_DIM     512
#define NUM_CLASSES  1000
#define KC           2
#define THREADS      128
#define WARPS_PER_BLOCK (THREADS / 32)
#define SPW          16                          // samples per warp
#define BLOCKS       (BATCH / (WARPS_PER_BLOCK * SPW))   // 512
#define PFD          4                           // L2 prefetch distance (samples)

// Scratch via __device__ globals (allocation-free, static zero-init; the last
// block resets them after finalizing, so every replay starts clean).
__device__ double        g_acc;
__device__ unsigned int  g_count;

__global__ __launch_bounds__(THREADS, 4) void mcl_main(
    const float* __restrict__ x,
    const void*  __restrict__ labels,
    const float* __restrict__ centers,
    float*       __restrict__ out)
{
    const int tid  = threadIdx.x;
    const int lane = tid & 31;
    const int warp_local = tid >> 5;

    // ---- label dtype detection (int32 vs int64), per block, ~free ----
    int v = 0;
    #pragma unroll
    for (int k = 0; k < 512 / THREADS; k++)
        v |= ((const int*)labels)[2 * (tid + k * THREADS) + 1];
    const int is64 = __syncthreads_or(v != 0) ? 0 : 1;

    const int warp_id = blockIdx.x * WARPS_PER_BLOCK + warp_local;
    const int base = warp_id * SPW;

    // ---- prefetch all 16 labels in one coalesced access ----
    int my_lbl = 0;
    if (lane < SPW) {
        long long l;
        if (is64) l = ((const long long*)labels)[base + lane];
        else      l = (long long)((const int*)labels)[base + lane];
        if (l < 0 || l >= NUM_CLASSES) l = 0;    // defensive clamp
        my_lbl = (int)l;
    }

    // ---- L2 prefetch of an x row (no destination reg, no scoreboard) ----
    #define PREFETCH_L2(s)                                                     \
        do {                                                                   \
            const float* xp_ = x + (size_t)(base + (s)) * FEAT_DIM;            \
            _Pragma("unroll")                                                  \
            for (int i_ = 0; i_ < 4; i_++)                                     \
                asm volatile("prefetch.global.L2 [%0];" ::                     \
                             "l"(xp_ + (lane + 32 * i_) * 4));                 \
        } while (0)

    // ---- ping-pong register buffers: x row + both centers (96 regs) ----
    float4 xb[2][4], ab[2][4], bb[2][4];

    #define PREFETCH(s, buf)                                                   \
        do {                                                                   \
            const float4* __restrict__ xr_ = reinterpret_cast<const float4*>( \
                x + (size_t)(base + (s)) * FEAT_DIM);                          \
            const int lbl_ = __shfl_sync(0xffffffffu, my_lbl, (s));            \
            const float4* __restrict__ c0_ = reinterpret_cast<const float4*>( \
                centers + (size_t)lbl_ * (KC * FEAT_DIM));                     \
            const float4* __restrict__ c1_ = c0_ + (FEAT_DIM / 4);             \
            _Pragma("unroll")                                                  \
            for (int i_ = 0; i_ < 4; i_++) {                                   \
                xb[buf][i_] = xr_[lane + 32 * i_];                             \
                ab[buf][i_] = c0_[lane + 32 * i_];                             \
                bb[buf][i_] = c1_[lane + 32 * i_];                             \
            }                                                                  \
        } while (0)

    // Warm the L2 pipeline for samples 1..PFD, register-load sample 0.
    #pragma unroll
    for (int s = 1; s <= PFD; s++) PREFETCH_L2(s);
    PREFETCH(0, 0);

    float sum_pair = 0.0f;     // lane-partial of sum over samples of (d0 + d1)
    float sum_absdiff = 0.0f;  // uniform across lanes: sum of |d0 - d1|

    #pragma unroll
    for (int s = 0; s < SPW; s++) {
        const int cur = s & 1;
        // Register-prefetch next sample (loads fly during compute below);
        // L2-prefetch PFD ahead so the register load will be an L2 hit.
        if (s + 1 < SPW) PREFETCH(s + 1, (s + 1) & 1);
        if (s + 1 + PFD < SPW) PREFETCH_L2(s + 1 + PFD);

        float d0 = 0.0f, d1 = 0.0f;
        #pragma unroll
        for (int i = 0; i < 4; i++) {
            const float4 xv = xb[cur][i];
            const float4 a  = ab[cur][i];
            const float4 b  = bb[cur][i];
            float t;
            t = xv.x - a.x; d0 = fmaf(t, t, d0);
            t = xv.y - a.y; d0 = fmaf(t, t, d0);
            t = xv.z - a.z; d0 = fmaf(t, t, d0);
            t = xv.w - a.w; d0 = fmaf(t, t, d0);
            t = xv.x - b.x; d1 = fmaf(t, t, d1);
            t = xv.y - b.y; d1 = fmaf(t, t, d1);
            t = xv.z - b.z; d1 = fmaf(t, t, d1);
            t = xv.w - b.w; d1 = fmaf(t, t, d1);
        }
        // min(d0,d1) = 0.5*((d0+d1) - |d0-d1|):
        //  - (d0+d1) lane-partials accumulate; ONE tree at warp end.
        //  - only (d0-d1) needs a per-sample 5-shfl tree.
        sum_pair += d0 + d1;
        float diff = d0 - d1;
        #pragma unroll
        for (int off = 16; off > 0; off >>= 1)
            diff += __shfl_xor_sync(0xffffffffu, diff, off);
        sum_absdiff += fabsf(diff);
    }
    #undef PREFETCH
    #undef PREFETCH_L2

    // Final warp reduction of the pair term (once for all 16 samples).
    #pragma unroll
    for (int off = 16; off > 0; off >>= 1)
        sum_pair += __shfl_xor_sync(0xffffffffu, sum_pair, off);
    const float total = 0.5f * (sum_pair - sum_absdiff);   // uniform on all lanes

    // ---- block reduce + single device accumulate ----
    __shared__ float s_part[WARPS_PER_BLOCK];
    __shared__ float s_last;
    if (lane == 0) s_part[warp_local] = total;
    __syncthreads();

    if (tid == 0) {
        float block_sum = 0.0f;
        #pragma unroll
        for (int i = 0; i < WARPS_PER_BLOCK; i++) block_sum += s_part[i];
        atomicAdd(&g_acc, (double)block_sum);
        __threadfence();
        unsigned int done = atomicAdd(&g_count, 1u);
        s_last = (done == gridDim.x - 1) ? 1.0f : 0.0f;
    }
    __syncthreads();

    // Last block: finalize mean, then reset state for the next replay.
    if (s_last != 0.0f && tid == 0) {
        out[0] = (float)(g_acc / (double)BATCH);
        g_acc = 0.0;
        g_count = 0u;
    }
}

extern "C" void kernel_launch(void* const* d_in, const int* in_sizes, int n_in,
                              void* d_out, int out_size)
{
    // Identify inputs by element count (robust to ordering):
    //   x: 32768*512 = 16777216, centers: 2000*512 = 1024000, labels: 32768.
    const float* x       = nullptr;
    const void*  labels  = nullptr;
    const float* centers = nullptr;
    for (int i = 0; i < n_in; i++) {
        if (in_sizes[i] == BATCH * FEAT_DIM)                 x = (const float*)d_in[i];
        else if (in_sizes[i] == NUM_CLASSES * KC * FEAT_DIM) centers = (const float*)d_in[i];
        else if (in_sizes[i] == BATCH)                       labels = d_in[i];
    }
    float* out = (float*)d_out;

    mcl_main<<<BLOCKS, THREADS>>>(x, labels, centers, out);
}